// round 7
// baseline (speedup 1.0000x reference)
#include <cuda_runtime.h>
#include <cuda_bf16.h>
#include <math.h>
#include <stddef.h>
#include <stdint.h>

#define D 512
#define LSEQ 1024
#define BATCH 8
#define NH 8
#define HD 64
#define ROWS (BATCH*LSEQ)   /* 8192 */
#define BH (BATCH*NH)       /* 64   */
#define DD (D*D)

// ---------------- scratch (no allocations allowed) ----------------
__device__ __nv_bfloat16 g_x1b[ROWS*D];
__device__ __nv_bfloat16 g_x2b[ROWS*D];
__device__ __nv_bfloat16 g_qb[ROWS*D];
__device__ __nv_bfloat16 g_kvb[(size_t)ROWS*2*D];
__device__ __nv_bfloat16 g_ctxb[ROWS*D];
__device__ __nv_bfloat16 g_hidb[(size_t)2*ROWS*2*D];
__device__ __nv_bfloat16 g_xlnb[(size_t)2*ROWS*D];
__device__ __nv_bfloat16 g_wb[(size_t)12*DD];
__device__ float g_proj[ROWS*D];
__device__ float g_ffn[(size_t)2*ROWS*D];

// weight offsets in g_wb
#define WB_W1  0           /* win1: 3DD */
#define WB_WO1 (3*DD)      /* wout1: DD */
#define WB_W2  (4*DD)      /* win2: 3DD */
#define WB_WO2 (7*DD)      /* wout2: DD */
#define WB_F1  (8*DD)      /* fw1: 2DD  */
#define WB_F2  (10*DD)     /* fw2: 2DD  */

// ======================= helpers =======================
__device__ __forceinline__ uint32_t smem_u32(const void* p) {
  uint32_t a;
  asm("{ .reg .u64 t; cvta.to.shared.u64 t, %1; cvt.u32.u64 %0, t; }"
      : "=r"(a) : "l"(p));
  return a;
}

#define CP_ASYNC16(dst, src) \
  asm volatile("cp.async.cg.shared.global [%0], [%1], 16;" \
               :: "r"(dst), "l"(src))
#define CP_COMMIT() asm volatile("cp.async.commit_group;")
#define CP_WAIT(n)  asm volatile("cp.async.wait_group %0;" :: "n"(n))

#define LDSM_X4(r0, r1, r2, r3, addr) \
  asm volatile("ldmatrix.sync.aligned.m8n8.x4.shared.b16 {%0,%1,%2,%3}, [%4];" \
               : "=r"(r0), "=r"(r1), "=r"(r2), "=r"(r3) : "r"(addr))
#define LDSM_X4_T(r0, r1, r2, r3, addr) \
  asm volatile("ldmatrix.sync.aligned.m8n8.x4.trans.shared.b16 {%0,%1,%2,%3}, [%4];" \
               : "=r"(r0), "=r"(r1), "=r"(r2), "=r"(r3) : "r"(addr))

#define MMA_BF16(c, a, b) \
  asm volatile( \
    "mma.sync.aligned.m16n8k16.row.col.f32.bf16.bf16.f32 " \
    "{%0,%1,%2,%3}, {%4,%5,%6,%7}, {%8,%9}, {%0,%1,%2,%3};" \
    : "+f"((c)[0]), "+f"((c)[1]), "+f"((c)[2]), "+f"((c)[3]) \
    : "r"((a)[0]), "r"((a)[1]), "r"((a)[2]), "r"((a)[3]), \
      "r"((b)[0]), "r"((b)[1]))

// ---------------- fp32 -> bf16 convert (n multiple of 4) ----------------
__global__ void __launch_bounds__(256) f2bf(
    const float* __restrict__ x, __nv_bfloat16* __restrict__ y)
{
  int i = blockIdx.x * 256 + threadIdx.x;
  float4 v = ((const float4*)x)[i];
  __nv_bfloat162 a = __floats2bfloat162_rn(v.x, v.y);
  __nv_bfloat162 b = __floats2bfloat162_rn(v.z, v.w);
  ((uint2*)y)[i] = make_uint2(*(uint32_t*)&a, *(uint32_t*)&b);
}

// ======================= bf16 GEMM, cp.async 3-stage pipeline =============
// C = A[M,K] @ B[N,K]^T + bias; A,B bf16; outputs: Cf (fp32, opt), Cb (bf16, opt).
// Tiles 128x128x32. 8 warps 4(M)x2(N). 3 stages -> 61.5KB smem -> 2 CTA/SM.
__global__ void __launch_bounds__(256, 2) gemm_bf16(
    const __nv_bfloat16* __restrict__ A, const __nv_bfloat16* __restrict__ B,
    const float* __restrict__ bias, float* __restrict__ Cf,
    __nv_bfloat16* __restrict__ Cb,
    int nslab, int lda, int ldb, int ldc, int relu)
{
  __shared__ __align__(16) __nv_bfloat16 As[3][128][40];
  __shared__ __align__(16) __nv_bfloat16 Bs[3][128][40];

  const int tid = threadIdx.x;
  const int wid = tid >> 5, l = tid & 31;
  const int warp_m = wid & 3, warp_n = wid >> 2;

  const int bm = blockIdx.y * 128;
  const int bn = blockIdx.x * 128;

  float acc[2][8][4];
  #pragma unroll
  for (int i = 0; i < 2; i++)
    #pragma unroll
    for (int j = 0; j < 8; j++)
      #pragma unroll
      for (int k = 0; k < 4; k++) acc[i][j][k] = 0.f;

  auto issue = [&](int slab, int stg) {
    const int k0 = slab << 5;
    #pragma unroll
    for (int it = 0; it < 2; ++it) {
      int idx = tid + it * 256;
      int r = idx >> 2, c = (idx & 3) << 3;
      CP_ASYNC16(smem_u32(&As[stg][r][c]),
                 A + (size_t)(bm + r) * lda + k0 + c);
    }
    #pragma unroll
    for (int it = 0; it < 2; ++it) {
      int idx = tid + it * 256;
      int r = idx >> 2, c = (idx & 3) << 3;
      CP_ASYNC16(smem_u32(&Bs[stg][r][c]),
                 B + (size_t)(bn + r) * ldb + k0 + c);
    }
    CP_COMMIT();
  };

  issue(0, 0);
  if (nslab > 1) issue(1, 1); else CP_COMMIT();

  int stg = 0;
  for (int i = 0; i < nslab; i++) {
    CP_WAIT(1);
    __syncthreads();
    const int buf = stg;
    stg = (stg == 2) ? 0 : stg + 1;
    if (i + 2 < nslab) {
      int nstg = (buf + 2) % 3;
      issue(i + 2, nstg);
    } else {
      CP_COMMIT();
    }

    const uint32_t a_base = smem_u32(&As[buf][0][0]);
    const uint32_t b_base = smem_u32(&Bs[buf][0][0]);
    #pragma unroll
    for (int ks = 0; ks < 2; ks++) {
      const int k0 = ks * 16;
      uint32_t afr[2][4];
      #pragma unroll
      for (int mf = 0; mf < 2; mf++) {
        int row = warp_m * 32 + mf * 16 + (l & 15);
        uint32_t addr = a_base + (uint32_t)(row * 80 + (k0 + ((l >> 4) << 3)) * 2);
        LDSM_X4(afr[mf][0], afr[mf][1], afr[mf][2], afr[mf][3], addr);
      }
      uint32_t bfr[8][2];
      #pragma unroll
      for (int nf = 0; nf < 8; nf += 2) {
        int row = warp_n * 64 + nf * 8 + ((l >> 4) << 3) + (l & 7);
        int col = k0 + ((l >> 3) & 1) * 8;
        uint32_t addr = b_base + (uint32_t)(row * 80 + col * 2);
        LDSM_X4(bfr[nf][0], bfr[nf][1], bfr[nf + 1][0], bfr[nf + 1][1], addr);
      }
      #pragma unroll
      for (int mf = 0; mf < 2; mf++)
        #pragma unroll
        for (int nf = 0; nf < 8; nf++)
          MMA_BF16(acc[mf][nf], afr[mf], bfr[nf]);
    }
  }

  const int gid = l >> 2, tig = l & 3;
  #pragma unroll
  for (int mf = 0; mf < 2; mf++) {
    const int row = bm + warp_m * 32 + mf * 16 + gid;
    #pragma unroll
    for (int nf = 0; nf < 8; nf++) {
      const int col = bn + warp_n * 64 + nf * 8 + tig * 2;
      float2 bv = make_float2(0.f, 0.f);
      if (bias) bv = *(const float2*)(bias + col);
      float2 v0, v1;
      v0.x = acc[mf][nf][0] + bv.x;
      v0.y = acc[mf][nf][1] + bv.y;
      v1.x = acc[mf][nf][2] + bv.x;
      v1.y = acc[mf][nf][3] + bv.y;
      if (relu) {
        v0.x = fmaxf(v0.x, 0.f); v0.y = fmaxf(v0.y, 0.f);
        v1.x = fmaxf(v1.x, 0.f); v1.y = fmaxf(v1.y, 0.f);
      }
      if (Cf) {
        *(float2*)(Cf + (size_t)row * ldc + col) = v0;
        *(float2*)(Cf + (size_t)(row + 8) * ldc + col) = v1;
      }
      if (Cb) {
        __nv_bfloat162 h0 = __floats2bfloat162_rn(v0.x, v0.y);
        __nv_bfloat162 h1 = __floats2bfloat162_rn(v1.x, v1.y);
        *(uint32_t*)(Cb + (size_t)row * ldc + col) = *(uint32_t*)&h0;
        *(uint32_t*)(Cb + (size_t)(row + 8) * ldc + col) = *(uint32_t*)&h1;
      }
    }
  }
}

// ======================= fused attention v2 ================================
// 8 warps, each owns 16 q-rows and the FULL 128 S-columns of a tile.
// P stays in registers (acc -> A-frag identity); no P smem round-trip.
// SMEM: Qs 18432 | Ks 2x18432 | Vs 18432 | Zs 512  => 74240 B -> 2 CTA/SM.
#define FA_QS   0
#define FA_KS   18432
#define FA_VS   55296
#define FA_ZS   73728
#define FA_SMEM 74240
#define FA_KSTRIDE 18432

__global__ void __launch_bounds__(256, 2) fused_attn(
    const __nv_bfloat16* __restrict__ Q, const __nv_bfloat16* __restrict__ KV,
    float* __restrict__ attn, __nv_bfloat16* __restrict__ ctxb)
{
  extern __shared__ char sm[];
  float* Zs = (float*)(sm + FA_ZS);                   // [128]

  const int tid = threadIdx.x;
  const int wid = tid >> 5, l = tid & 31;
  const int gid = l >> 2, tig = l & 3;

  const int z = blockIdx.y;
  const int b = z >> 3, h = z & 7;
  const int l0 = blockIdx.x * 128;

  const __nv_bfloat16* Qg = Q  + (size_t)b * LSEQ * D + h * HD;     // stride D
  const __nv_bfloat16* Kg = KV + (size_t)b * LSEQ * 2 * D + h * HD; // stride 2D
  const __nv_bfloat16* Vg = Kg + D;
  float* Pg = attn + (size_t)z * LSEQ * LSEQ;
  __nv_bfloat16* Ogb = ctxb + (size_t)b * LSEQ * D + h * HD;

  const uint32_t qsb = smem_u32(sm + FA_QS);
  const uint32_t ks0 = smem_u32(sm + FA_KS);
  const uint32_t vsb = smem_u32(sm + FA_VS);

  auto issue_q = [&]() {
    #pragma unroll
    for (int it = 0; it < 4; ++it) {
      int idx = tid + it * 256;
      int r = idx >> 3, c = (idx & 7) << 3;
      CP_ASYNC16(qsb + (uint32_t)(r * 144 + c * 2),
                 Qg + (size_t)(l0 + r) * D + c);
    }
    CP_COMMIT();
  };
  auto issue_k = [&](int s0, int kb) {
    const uint32_t base = ks0 + kb * FA_KSTRIDE;
    #pragma unroll
    for (int it = 0; it < 4; ++it) {
      int idx = tid + it * 256;
      int r = idx >> 3, c = (idx & 7) << 3;
      CP_ASYNC16(base + (uint32_t)(r * 144 + c * 2),
                 Kg + (size_t)(s0 + r) * 2 * D + c);
    }
    CP_COMMIT();
  };
  auto issue_v = [&](int s0) {
    #pragma unroll
    for (int it = 0; it < 4; ++it) {
      int idx = tid + it * 256;
      int r = idx >> 3, c = (idx & 7) << 3;
      CP_ASYNC16(vsb + (uint32_t)(r * 144 + c * 2),
                 Vg + (size_t)(s0 + r) * 2 * D + c);
    }
    CP_COMMIT();
  };

  issue_q();
  issue_k(0, 0);

  // S half: acc[8][4] covers n-cols [half*64, half*64+64) for this warp's 16 rows
  auto s_half = [&](float (*acc)[4], int kb, int half) {
    const uint32_t ksb = ks0 + kb * FA_KSTRIDE;
    #pragma unroll
    for (int j = 0; j < 8; j++)
      #pragma unroll
      for (int k = 0; k < 4; k++) acc[j][k] = 0.f;
    #pragma unroll
    for (int ks = 0; ks < 4; ks++) {
      const int k0 = ks * 16;
      uint32_t afr[4];
      {
        int row = wid * 16 + (l & 15);
        uint32_t addr = qsb + (uint32_t)(row * 144 + (k0 + ((l >> 4) << 3)) * 2);
        LDSM_X4(afr[0], afr[1], afr[2], afr[3], addr);
      }
      uint32_t bfr[8][2];
      #pragma unroll
      for (int nf = 0; nf < 8; nf += 2) {
        int row = half * 64 + nf * 8 + ((l >> 4) << 3) + (l & 7);
        int col = k0 + ((l >> 3) & 1) * 8;
        uint32_t addr = ksb + (uint32_t)(row * 144 + col * 2);
        LDSM_X4(bfr[nf][0], bfr[nf][1], bfr[nf + 1][0], bfr[nf + 1][1], addr);
      }
      #pragma unroll
      for (int nf = 0; nf < 8; nf++)
        MMA_BF16(acc[nf], afr, bfr[nf]);
    }
  };

  // ================= pass 1: row sums =================
  {
    float zr[2] = {0.f, 0.f};
    for (int st = 0; st < 8; st++) {
      const int kb = st & 1;
      CP_WAIT(0);
      __syncthreads();
      if (st < 7) issue_k((st + 1) * 128, kb ^ 1); else CP_COMMIT();
      #pragma unroll
      for (int half = 0; half < 2; half++) {
        float acc[8][4];
        s_half(acc, kb, half);
        #pragma unroll
        for (int nf = 0; nf < 8; nf++) {
          zr[0] += __expf(acc[nf][0] * 0.125f) + __expf(acc[nf][1] * 0.125f);
          zr[1] += __expf(acc[nf][2] * 0.125f) + __expf(acc[nf][3] * 0.125f);
        }
      }
    }
    #pragma unroll
    for (int rp = 0; rp < 2; rp++) {
      float v = zr[rp];
      v += __shfl_xor_sync(0xffffffffu, v, 1);
      v += __shfl_xor_sync(0xffffffffu, v, 2);
      if (tig == 0) Zs[wid * 16 + rp * 8 + gid] = v;
    }
    __syncthreads();
    if (tid < 128) Zs[tid] = 1.f / Zs[tid];
    issue_k(0, 0);
    issue_v(0);
    __syncthreads();
  }

  float iz[2];
  iz[0] = Zs[wid * 16 + gid];
  iz[1] = Zs[wid * 16 + 8 + gid];

  // ================= pass 2: write P, accumulate O = P@V =================
  float oacc[8][4];
  #pragma unroll
  for (int j = 0; j < 8; j++)
    #pragma unroll
    for (int k = 0; k < 4; k++) oacc[j][k] = 0.f;

  for (int st = 0; st < 8; st++) {
    const int s0 = st * 128;
    const int kb = st & 1;
    CP_WAIT(1);                 // K(st) ready (V(st) in flight)
    __syncthreads();
    if (st < 7) issue_k(s0 + 128, kb ^ 1); else CP_COMMIT();

    uint32_t pk[8][4];          // packed P A-frags: kk=0..7 covers S-cols kk*16..+15
    #pragma unroll
    for (int half = 0; half < 2; half++) {
      float acc[8][4];
      s_half(acc, kb, half);
      #pragma unroll
      for (int nf = 0; nf < 8; nf++) {
        const int gnf = half * 8 + nf;
        const int c = gnf * 8 + tig * 2;
        const int r0 = wid * 16 + gid;
        float p00 = __expf(acc[nf][0] * 0.125f) * iz[0];
        float p01 = __expf(acc[nf][1] * 0.125f) * iz[0];
        float p10 = __expf(acc[nf][2] * 0.125f) * iz[1];
        float p11 = __expf(acc[nf][3] * 0.125f) * iz[1];
        *(float2*)(Pg + (size_t)(l0 + r0) * LSEQ + s0 + c) = make_float2(p00, p01);
        *(float2*)(Pg + (size_t)(l0 + r0 + 8) * LSEQ + s0 + c) = make_float2(p10, p11);
        __nv_bfloat162 q0 = __floats2bfloat162_rn(p00, p01);
        __nv_bfloat162 q1 = __floats2bfloat162_rn(p10, p11);
        const int kk = gnf >> 1;
        if ((gnf & 1) == 0) {
          pk[kk][0] = *(uint32_t*)&q0;
          pk[kk][1] = *(uint32_t*)&q1;
        } else {
          pk[kk][2] = *(uint32_t*)&q0;
          pk[kk][3] = *(uint32_t*)&q1;
        }
      }
    }
    CP_WAIT(1);                 // V(st) ready (K(st+1) in flight)
    __syncthreads();

    // O += P @ V  (full k per warp; B = V^T via ldmatrix.trans)
    #pragma unroll
    for (int kk = 0; kk < 8; kk++) {
      uint32_t bfr[8][2];
      #pragma unroll
      for (int nf = 0; nf < 8; nf += 2) {
        int krow = kk * 16 + ((l >> 3) & 1) * 8 + (l & 7);
        int ncol = nf * 8 + ((l >> 4) << 3);
        uint32_t addr = vsb + (uint32_t)(krow * 144 + ncol * 2);
        LDSM_X4_T(bfr[nf][0], bfr[nf][1], bfr[nf + 1][0], bfr[nf + 1][1], addr);
      }
      #pragma unroll
      for (int nf = 0; nf < 8; nf++)
        MMA_BF16(oacc[nf], pk[kk], bfr[nf]);
    }
    __syncthreads();            // all warps done reading Vs
    if (st < 7) issue_v(s0 + 128); else CP_COMMIT();
  }
  CP_WAIT(0);

  // ---- write ctx (bf16) ----
  {
    const int r0 = l0 + wid * 16 + gid;
    #pragma unroll
    for (int nf = 0; nf < 8; nf++) {
      const int c = nf * 8 + tig * 2;
      __nv_bfloat162 h0 = __floats2bfloat162_rn(oacc[nf][0], oacc[nf][1]);
      __nv_bfloat162 h1 = __floats2bfloat162_rn(oacc[nf][2], oacc[nf][3]);
      *(uint32_t*)(Ogb + (size_t)r0 * D + c) = *(uint32_t*)&h0;
      *(uint32_t*)(Ogb + (size_t)(r0 + 8) * D + c) = *(uint32_t*)&h1;
    }
  }
}

// ---------------- out = LN(x + y) * g + b, rows of 512 ----------------
__global__ void __launch_bounds__(256) residual_ln_kernel(
    const float* __restrict__ x, const float* __restrict__ y,
    const float* __restrict__ g, const float* __restrict__ b,
    float* __restrict__ out, __nv_bfloat16* __restrict__ outb)
{
  __shared__ float shs[8], shq[8];
  const size_t row = blockIdx.x;
  const int t = threadIdx.x;
  float2 xa = ((const float2*)x)[row * 256 + t];
  float2 ya = ((const float2*)y)[row * 256 + t];
  float v0 = xa.x + ya.x, v1 = xa.y + ya.y;
  float s = v0 + v1, q = v0*v0 + v1*v1;
  #pragma unroll
  for (int o = 16; o > 0; o >>= 1) {
    s += __shfl_xor_sync(0xffffffffu, s, o);
    q += __shfl_xor_sync(0xffffffffu, q, o);
  }
  if ((t & 31) == 0) { shs[t >> 5] = s; shq[t >> 5] = q; }
  __syncthreads();
  s = 0.f; q = 0.f;
  #pragma unroll
  for (int i = 0; i < 8; i++) { s += shs[i]; q += shq[i]; }
  float mu  = s * (1.f / 512.f);
  float var = q * (1.f / 512.f) - mu * mu;
  float inv = rsqrtf(var + 1e-5f);
  float2 gg = ((const float2*)g)[t];
  float2 bb = ((const float2*)b)[t];
  float2 o2;
  o2.x = (v0 - mu) * inv * gg.x + bb.x;
  o2.y = (v1 - mu) * inv * gg.y + bb.y;
  ((float2*)out)[row * 256 + t] = o2;
  if (outb) {
    __nv_bfloat162 h = __floats2bfloat162_rn(o2.x, o2.y);
    ((uint32_t*)outb)[row * 256 + t] = *(uint32_t*)&h;
  }
}

// ---------------- host-side orchestration ----------------
extern "C" void kernel_launch(void* const* d_in, const int* in_sizes, int n_in,
                              void* d_out, int out_size)
{
  const float* x1    = (const float*)d_in[0];
  const float* x2    = (const float*)d_in[1];
  const float* win1  = (const float*)d_in[2];
  const float* bin1  = (const float*)d_in[3];
  const float* wout1 = (const float*)d_in[4];
  const float* bout1 = (const float*)d_in[5];
  const float* win2  = (const float*)d_in[6];
  const float* bin2  = (const float*)d_in[7];
  const float* wout2 = (const float*)d_in[8];
  const float* bout2 = (const float*)d_in[9];
  const float* g1    = (const float*)d_in[10];
  const float* b1    = (const float*)d_in[11];
  const float* g2    = (const float*)d_in[12];
  const float* b2    = (const float*)d_in[13];
  const float* fw1   = (const float*)d_in[14];
  const float* fb1   = (const float*)d_in[15];
  const float* fw2   = (const float*)d_in[16];
  const float* fb2   = (const float*)d_in[17];
  const float* g3    = (const float*)d_in[18];
  const float* b3    = (const float*)d_in[19];

  cudaFuncSetAttribute(fused_attn, cudaFuncAttributeMaxDynamicSharedMemorySize, FA_SMEM);

  float* out = (float*)d_out;
  float* ox1 = out;
  float* ox2 = out + (size_t)ROWS * D;
  float* w12 = out + (size_t)2 * ROWS * D;
  float* w21 = w12 + (size_t)BH * LSEQ * LSEQ;

  __nv_bfloat16 *x1b, *x2b, *qb, *kvb, *ctxb, *hidb, *xlnb, *wb;
  float *proj, *ffn;
  cudaGetSymbolAddress((void**)&x1b,  g_x1b);
  cudaGetSymbolAddress((void**)&x2b,  g_x2b);
  cudaGetSymbolAddress((void**)&qb,   g_qb);
  cudaGetSymbolAddress((void**)&kvb,  g_kvb);
  cudaGetSymbolAddress((void**)&ctxb, g_ctxb);
  cudaGetSymbolAddress((void**)&hidb, g_hidb);
  cudaGetSymbolAddress((void**)&xlnb, g_xlnb);
  cudaGetSymbolAddress((void**)&wb,   g_wb);
  cudaGetSymbolAddress((void**)&proj, g_proj);
  cudaGetSymbolAddress((void**)&ffn,  g_ffn);

  f2bf<<<ROWS*D/1024, 256>>>(x1, x1b);                                   // 0
  f2bf<<<ROWS*D/1024, 256>>>(x2, x2b);                                   // 1
  f2bf<<<3*DD/1024, 256>>>(win1,  wb + WB_W1);                           // 2
  gemm_bf16<<<dim3(4, 64), 256>>>(x1b, wb + WB_W1, bin1, nullptr, qb,    // 3
                                  16, D, D, D, 0);
  gemm_bf16<<<dim3(8, 64), 256>>>(x2b, wb + WB_W1 + DD, bin1 + D,        // 4
                                  nullptr, kvb, 16, D, D, 2*D, 0);
  fused_attn<<<dim3(8, BH), 256, FA_SMEM>>>(qb, kvb, w12, ctxb);         // 5
  f2bf<<<DD/1024,   256>>>(wout1, wb + WB_WO1);                          // 6
  gemm_bf16<<<dim3(4, 64), 256>>>(ctxb, wb + WB_WO1, bout1, proj,        // 7
                                  nullptr, 16, D, D, D, 0);
  residual_ln_kernel<<<ROWS, 256>>>(x1, proj, g1, b1, ox1, xlnb);        // 8

  f2bf<<<3*DD/1024, 256>>>(win2,  wb + WB_W2);                           // 9
  gemm_bf16<<<dim3(4, 64), 256>>>(x2b, wb + WB_W2, bin2, nullptr, qb,    // 10
                                  16, D, D, D, 0);
  gemm_bf16<<<dim3(8, 64), 256>>>(xlnb, wb + WB_W2 + DD, bin2 + D,       // 11
                                  nullptr, kvb, 16, D, D, 2*D, 0);
  fused_attn<<<dim3(8, BH), 256, FA_SMEM>>>(qb, kvb, w21, ctxb);         // 12
  f2bf<<<DD/1024,   256>>>(wout2, wb + WB_WO2);                          // 13
  gemm_bf16<<<dim3(4, 64), 256>>>(ctxb, wb + WB_WO2, bout2, proj,        // 14
                                  nullptr, 16, D, D, D, 0);
  residual_ln_kernel<<<ROWS, 256>>>(x2, proj, g2, b2, ox2,               // 15
                                    xlnb + (size_t)ROWS * D);

  f2bf<<<2*DD/1024, 256>>>(fw1, wb + WB_F1);                             // 16
  f2bf<<<2*DD/1024, 256>>>(fw2, wb + WB_F2);                             // 17
  gemm_bf16<<<dim3(8, 128), 256>>>(xlnb, wb + WB_F1, fb1, nullptr, hidb, // 18
                                   16, D, D, 2*D, 1);
  gemm_bf16<<<dim3(4, 128), 256>>>(hidb, wb + WB_F2, fb2, ffn, nullptr,  // 19
                                   32, 2*D, 2*D, D, 0);
  residual_ln_kernel<<<2*ROWS, 256>>>(out, ffn, g3, b3, out, nullptr);   // 20
}